// round 7
// baseline (speedup 1.0000x reference)
#include <cuda_runtime.h>
#include <stdint.h>

#define NBATCH 8
#define NCLS   80
#define ROWS   17328                  // A*HW = 3*5776
#define PERB   (ROWS * NCLS)          // 1386240 elements per batch
#define NTOT   (NBATCH * PERB)        // 11089920
#define N4     (NTOT / 4)             // 2772480 float4s
#define TOPK   200
#define CAP    1024                   // sort buffer capacity (fallback)
#define CAP_G  768                    // global per-(b,c) candidate list capacity
#define KW     7                      // words actually used for bitmasks
#define KW8    8                      // padded stride (uint4 x2 per row)
#define NBC    (NBATCH * NCLS)
#define NFINE  9
#define NLAD   11
#define SCAT_E   10
#define SCAT_BLK 1083                 // 1083*256*10 = 2772480 = N4 exactly

// Global scratch (static, zero-initialized at module load)
__device__ unsigned long long g_cand[NBC * CAP_G];   // ~3.9 MB
__device__ int g_ccnt[NBC];                          // reset by nms each run

__device__ __forceinline__ unsigned long long make_key(float v, int idx) {
    return ((unsigned long long)__float_as_uint(v) << 32) | (unsigned int)(~idx);
}

// ---------------------------------------------------------------------------
// Kernel 1: flat coalesced scan, exact-fit grid (no bounds checks).
// Pushes >0.98 candidates into per-(b,c) global lists; the atomic IS the count.
// ---------------------------------------------------------------------------
__global__ void __launch_bounds__(256) scatter_kernel(const float4* __restrict__ s4) {
    const int base = blockIdx.x * (SCAT_E * 256) + threadIdx.x;
    #pragma unroll
    for (int k = 0; k < SCAT_E; k++) {
        const int i4 = base + k * 256;
        float4 v = __ldcs(&s4[i4]);
        if (fmaxf(fmaxf(v.x, v.y), fmaxf(v.z, v.w)) > 0.98f) {
            float a[4] = {v.x, v.y, v.z, v.w};
            #pragma unroll
            for (int u = 0; u < 4; u++) {
                if (a[u] > 0.98f) {
                    int e   = i4 * 4 + u;
                    int b   = e / PERB;
                    int rem = e - b * PERB;
                    int row = rem / NCLS;
                    int cls = rem - row * NCLS;
                    int bc  = b * NCLS + cls;
                    int pos = atomicAdd(&g_ccnt[bc], 1);
                    if (pos < CAP_G) g_cand[bc * CAP_G + pos] = make_key(a[u], row);
                }
            }
        }
    }
}

// ---------------------------------------------------------------------------
// Kernel 2: one CTA per (batch, class). Refine pivot + sort + greedy NMS.
// ---------------------------------------------------------------------------
__global__ void __launch_bounds__(256) nms_kernel(const float* __restrict__ boxes,
                                                  const float* __restrict__ scores,
                                                  float* __restrict__ out) {
    const int tid  = threadIdx.x;
    const int lane = tid & 31;
    const int wid  = tid >> 5;
    const int bc   = blockIdx.x;
    const int b    = bc / NCLS;
    const int c    = bc % NCLS;

    __shared__ unsigned long long keys[CAP];
    __shared__ float4 s_box4[TOPK];
    __shared__ float s_area[TOPK], s_sc[TOPK];
    __shared__ unsigned int sup[(TOPK + 1) * KW8];
    __shared__ unsigned int s_keepw[KW];
    __shared__ int s_num, s_fcnt[NFINE], s_pcnt[NLAD];

    const int cnt098 = g_ccnt[bc];

    if (tid < NFINE) s_fcnt[tid] = 0;
    if (tid == 0) s_num = 0;
    __syncthreads();

    int cnt;
    if (cnt098 >= TOPK && cnt098 <= CAP_G) {
        // ---- Fast path: list is complete and holds >= 200 candidates.
        unsigned long long kreg[3];
        const unsigned long long* src = g_cand + (size_t)bc * CAP_G;
        #pragma unroll
        for (int r = 0; r < 3; r++) {
            int k = tid + r * 256;
            kreg[r] = (k < cnt098) ? src[k] : 0ull;
        }
        // Fine-level histogram on the candidate scores (registers only)
        const float FL[NFINE] = {0.99500f, 0.99375f, 0.99250f, 0.99125f, 0.99000f,
                                 0.98875f, 0.98750f, 0.98625f, 0.98500f};
        int lc[NFINE];
        #pragma unroll
        for (int f = 0; f < NFINE; f++) lc[f] = 0;
        #pragma unroll
        for (int r = 0; r < 3; r++) {
            float sc = __uint_as_float((unsigned int)(kreg[r] >> 32));
            #pragma unroll
            for (int f = 0; f < NFINE; f++) lc[f] += (sc > FL[f]);
        }
        #pragma unroll
        for (int f = 0; f < NFINE; f++) {
            int ws = __reduce_add_sync(0xffffffffu, lc[f]);
            if (lane == 0 && ws) atomicAdd(&s_fcnt[f], ws);
        }
        __syncthreads();
        // Finest level still holding >= 200 candidates
        float pivot = 0.98f;
        #pragma unroll
        for (int f = NFINE - 1; f >= 0; f--)
            if (s_fcnt[f] >= TOPK) pivot = FL[f];
        // Compact selected keys into the sort buffer
        #pragma unroll
        for (int r = 0; r < 3; r++) {
            float sc = __uint_as_float((unsigned int)(kreg[r] >> 32));
            if (sc > pivot) {
                int pos = atomicAdd(&s_num, 1);
                keys[pos] = kreg[r];
            }
        }
        __syncthreads();
        cnt = s_num;
    } else {
        // ---- Fallback (statistically never): full strided rescan with ladder.
        if (tid < NLAD) s_pcnt[tid] = 0;
        __syncthreads();
        const float PL[NLAD] = {0.9950f, 0.9925f, 0.9900f, 0.9875f, 0.9850f,
                                0.98f, 0.96f, 0.92f, 0.84f, 0.68f, 0.50f};
        const float* col = scores + (size_t)b * PERB + c;
        int lc[NLAD];
        #pragma unroll
        for (int l = 0; l < NLAD; l++) lc[l] = 0;
        for (int i = tid; i < ROWS; i += 256) {
            float v = col[(size_t)i * NCLS];
            #pragma unroll
            for (int l = 0; l < NLAD; l++) lc[l] += (v > PL[l]);
        }
        #pragma unroll
        for (int l = 0; l < NLAD; l++) {
            int ws = __reduce_add_sync(0xffffffffu, lc[l]);
            if (lane == 0 && ws) atomicAdd(&s_pcnt[l], ws);
        }
        __syncthreads();
        const int n05 = s_pcnt[NLAD - 1];
        const int target = (n05 < TOPK) ? n05 : TOPK;
        float pivot = 0.50f;
        #pragma unroll
        for (int l = NLAD - 1; l >= 0; l--)
            if (s_pcnt[l] >= target) pivot = PL[l];
        for (int i = tid; i < ROWS; i += 256) {
            float v = col[(size_t)i * NCLS];
            if (v > pivot) {
                int pos = atomicAdd(&s_num, 1);
                if (pos < CAP) keys[pos] = make_key(v, i);
            }
        }
        __syncthreads();
        cnt = s_num; if (cnt > CAP) cnt = CAP;
    }

    // ---- Sort descending. Typical path: register/shuffle bitonic on 256 keys
    //      (30 shfl steps, 6 smem steps). Fallback smem bitonic for cnt > 256.
    if (cnt <= 256) {
        for (int i = cnt + tid; i < 256; i += 256) keys[i] = 0ull;
        __syncthreads();
        unsigned long long key = keys[tid];
        #pragma unroll
        for (int k = 2; k <= 256; k <<= 1) {
            #pragma unroll
            for (int j = k >> 1; j > 0; j >>= 1) {
                unsigned long long other;
                if (j >= 32) {
                    keys[tid] = key;
                    __syncthreads();
                    other = keys[tid ^ j];
                    __syncthreads();
                } else {
                    other = __shfl_xor_sync(0xffffffffu, key, j);
                }
                bool keep_max = ((tid & k) == 0) == ((tid & j) == 0);
                key = ((key > other) == keep_max) ? key : other;
            }
        }
        keys[tid] = key;
        __syncthreads();
    } else {
        int P = 512; while (P < cnt) P <<= 1;
        for (int i = cnt + tid; i < P; i += 256) keys[i] = 0ull;
        __syncthreads();
        for (int k = 2; k <= P; k <<= 1) {
            for (int j = k >> 1; j > 0; j >>= 1) {
                for (int i = tid; i < P; i += 256) {
                    int l = i ^ j;
                    if (l > i) {
                        unsigned long long a = keys[i], d = keys[l];
                        bool sw = ((i & k) == 0) ? (a < d) : (a > d);
                        if (sw) { keys[i] = d; keys[l] = a; }
                    }
                }
                __syncthreads();
            }
        }
    }

    const int n_top = (cnt < TOPK) ? cnt : TOPK;

    // ---- Gather boxes for the top-200; also zero the padded sup array
    for (int k = tid; k < (TOPK + 1) * KW8 / 4; k += 256)
        ((uint4*)sup)[k] = make_uint4(0u, 0u, 0u, 0u);
    for (int k = tid; k < TOPK; k += 256) {
        if (k < n_top) {
            unsigned long long key = keys[k];
            int idx = (int)(~(unsigned int)(key & 0xffffffffull));
            float4 bb = ((const float4*)boxes)[(size_t)b * ROWS + idx];
            s_box4[k] = bb;
            s_area[k] = (bb.z - bb.x) * (bb.w - bb.y);
            s_sc[k]   = __uint_as_float((unsigned int)(key >> 32));
        } else {
            s_box4[k] = make_float4(0.f, 0.f, 0.f, 0.f);
            s_area[k] = 0.f; s_sc[k] = 0.f;
        }
    }
    __syncthreads();

    // ---- Suppression bitmask: one warp per row, ballot forms each 32-bit word.
    for (int r = wid; r < n_top; r += 8) {
        const float4 bi = s_box4[r];
        const float  ai = s_area[r];
        const int    w0 = r >> 5;
        for (int w = w0; w < KW; w++) {
            int j = w * 32 + lane;
            bool hit = false;
            if (j > r && j < n_top) {
                float4 bj = s_box4[j];
                float xx1 = fmaxf(bi.x, bj.x);
                float yy1 = fmaxf(bi.y, bj.y);
                float xx2 = fminf(bi.z, bj.z);
                float yy2 = fminf(bi.w, bj.w);
                float inter = fmaxf(0.f, xx2 - xx1) * fmaxf(0.f, yy2 - yy1);
                if (inter > 0.f) {
                    float un = (ai + s_area[j]) - inter;
                    hit = (inter / un) > 0.5f;
                }
            }
            unsigned int m = __ballot_sync(0xffffffffu, hit);
            if (lane == 0) sup[r * KW8 + w] = m;
        }
    }
    __syncthreads();

    // ---- Serial greedy on thread 0: rows as 2x uint4, prefetch row i+1.
    if (tid == 0) {
        const uint4* sv = (const uint4*)sup;
        unsigned int rem[KW8];
        #pragma unroll
        for (int w = 0; w < KW8; w++) rem[w] = 0u;
        uint4 n0 = sv[0], n1 = sv[1];
        #pragma unroll
        for (int w0 = 0; w0 < KW; w0++) {
            for (int ii = 0; ii < 32; ii++) {
                int idx = w0 * 32 + ii;
                if (idx >= n_top) break;
                uint4 c0 = n0, c1 = n1;
                n0 = sv[(idx + 1) * 2];
                n1 = sv[(idx + 1) * 2 + 1];
                if (((rem[w0] >> ii) & 1u) == 0u) {
                    rem[0] |= c0.x; rem[1] |= c0.y; rem[2] |= c0.z; rem[3] |= c0.w;
                    rem[4] |= c1.x; rem[5] |= c1.y; rem[6] |= c1.z;
                }
            }
        }
        #pragma unroll
        for (int w = 0; w < KW; w++) s_keepw[w] = ~rem[w];
        g_ccnt[bc] = 0;   // self-clean for next graph replay
    }
    __syncthreads();

    // ---- Write output: (b, c, k, 6) = [x1,y1,x2,y2,score,class] or zeros
    float* o = out + (size_t)bc * (TOPK * 6);
    const float cls = (float)c;
    for (int t = tid; t < TOPK * 6; t += 256) {
        int k = t / 6, f = t % 6;
        bool kp = (k < n_top) && (((s_keepw[k >> 5] >> (k & 31)) & 1u) != 0u);
        float v = 0.f;
        if (kp) {
            switch (f) {
                case 0: v = s_box4[k].x; break;
                case 1: v = s_box4[k].y; break;
                case 2: v = s_box4[k].z; break;
                case 3: v = s_box4[k].w; break;
                case 4: v = s_sc[k]; break;
                default: v = cls;   break;
            }
        }
        o[t] = v;
    }
}

// ---------------------------------------------------------------------------
extern "C" void kernel_launch(void* const* d_in, const int* in_sizes, int n_in,
                              void* d_out, int out_size) {
    const float* boxes  = (const float*)d_in[0];
    const float* scores = (const float*)d_in[1];
    if (n_in >= 2 && in_sizes[0] > in_sizes[1]) {  // scores is the bigger tensor
        boxes  = (const float*)d_in[1];
        scores = (const float*)d_in[0];
    }
    float* out = (float*)d_out;

    scatter_kernel<<<SCAT_BLK, 256>>>((const float4*)scores);
    nms_kernel<<<NBC, 256>>>(boxes, scores, out);
}

// round 8
// speedup vs baseline: 1.0773x; 1.0773x over previous
#include <cuda_runtime.h>
#include <stdint.h>

#define NBATCH 8
#define NCLS   80
#define ROWS   17328                  // A*HW = 3*5776
#define PERB   (ROWS * NCLS)          // 1386240 elements per batch
#define PERB4  (PERB / 4)             // 346560 float4 per batch
#define SLICE4 (PERB4 / NCLS)         // 4332 float4 per CTA scatter slice
#define TOPK   200
#define CAP    1024                   // sort buffer capacity (fallback)
#define CAP_G  768                    // global per-(b,c) candidate list capacity
#define KW     7                      // words actually used for bitmasks
#define KW8    8                      // padded stride (uint4 x2 per row)
#define NBC    (NBATCH * NCLS)
#define NFINE  9
#define NLAD   11

// Global scratch (static, zero-initialized at module load)
__device__ unsigned long long g_cand[NBC * CAP_G];   // ~3.9 MB
__device__ int g_ccnt[NBC];                          // reset by each CTA at end
__device__ int g_done[NBATCH];                       // monotonic barrier counters

__device__ __forceinline__ unsigned long long make_key(float v, int idx) {
    return ((unsigned long long)__float_as_uint(v) << 32) | (unsigned int)(~idx);
}

// ---------------------------------------------------------------------------
// Fused kernel: one CTA per (batch, class).
// Phase 1: scan 1/80 of this batch's scores, push >0.98 candidates.
// Phase 2: per-batch barrier, then pivot-refine + sort + greedy NMS.
// ---------------------------------------------------------------------------
__global__ void __launch_bounds__(256, 5)
fused_kernel(const float4* __restrict__ s4,
             const float*  __restrict__ boxes,
             const float*  __restrict__ scores,
             float*        __restrict__ out) {
    const int tid  = threadIdx.x;
    const int lane = tid & 31;
    const int wid  = tid >> 5;
    const int bc   = blockIdx.x;
    const int b    = bc / NCLS;
    const int c    = bc % NCLS;

    __shared__ unsigned long long keys[CAP];
    __shared__ float4 s_box4[TOPK];
    __shared__ float s_area[TOPK], s_sc[TOPK];
    __shared__ unsigned int sup[(TOPK + 1) * KW8];
    __shared__ unsigned int s_keepw[KW];
    __shared__ int s_num, s_fcnt[NFINE], s_pcnt[NLAD];

    // ================= Phase 1: scatter slice =================
    {
        const int slice0 = b * PERB4 + c * SLICE4;   // float4 index
        const float4* p = s4 + slice0;
        for (int i = tid; i < SLICE4; i += 256) {
            float4 v = __ldcs(&p[i]);
            if (fmaxf(fmaxf(v.x, v.y), fmaxf(v.z, v.w)) > 0.98f) {
                float a[4] = {v.x, v.y, v.z, v.w};
                #pragma unroll
                for (int u = 0; u < 4; u++) {
                    if (a[u] > 0.98f) {
                        int e    = (slice0 + i) * 4 + u;
                        int rem  = e - b * PERB;
                        int row  = rem / NCLS;
                        int cls  = rem - row * NCLS;
                        int dbc  = b * NCLS + cls;
                        int pos  = atomicAdd(&g_ccnt[dbc], 1);
                        if (pos < CAP_G) g_cand[dbc * CAP_G + pos] = make_key(a[u], row);
                    }
                }
            }
        }
    }
    // ---- Per-batch barrier: 80 arrivals on a monotonic counter.
    __syncthreads();
    if (tid == 0) {
        __threadfence();
        int old = atomicAdd(&g_done[b], 1);
        int target = old - (old % NCLS) + NCLS;
        while (atomicAdd(&g_done[b], 0) < target) __nanosleep(64);
        __threadfence();
    }
    __syncthreads();

    // ================= Phase 2: NMS for (b, c) =================
    const int cnt098 = g_ccnt[bc];

    if (tid < NFINE) s_fcnt[tid] = 0;
    if (tid == 0) s_num = 0;
    __syncthreads();

    int cnt;
    if (cnt098 >= TOPK && cnt098 <= CAP_G) {
        // ---- Fast path: list is complete and holds >= 200 candidates.
        unsigned long long kreg[3];
        const unsigned long long* src = g_cand + (size_t)bc * CAP_G;
        #pragma unroll
        for (int r = 0; r < 3; r++) {
            int k = tid + r * 256;
            kreg[r] = (k < cnt098) ? src[k] : 0ull;
        }
        const float FL[NFINE] = {0.99500f, 0.99375f, 0.99250f, 0.99125f, 0.99000f,
                                 0.98875f, 0.98750f, 0.98625f, 0.98500f};
        int lc[NFINE];
        #pragma unroll
        for (int f = 0; f < NFINE; f++) lc[f] = 0;
        #pragma unroll
        for (int r = 0; r < 3; r++) {
            float sc = __uint_as_float((unsigned int)(kreg[r] >> 32));
            #pragma unroll
            for (int f = 0; f < NFINE; f++) lc[f] += (sc > FL[f]);
        }
        #pragma unroll
        for (int f = 0; f < NFINE; f++) {
            int ws = __reduce_add_sync(0xffffffffu, lc[f]);
            if (lane == 0 && ws) atomicAdd(&s_fcnt[f], ws);
        }
        __syncthreads();
        float pivot = 0.98f;
        #pragma unroll
        for (int f = NFINE - 1; f >= 0; f--)
            if (s_fcnt[f] >= TOPK) pivot = FL[f];
        #pragma unroll
        for (int r = 0; r < 3; r++) {
            float sc = __uint_as_float((unsigned int)(kreg[r] >> 32));
            if (sc > pivot) {
                int pos = atomicAdd(&s_num, 1);
                keys[pos] = kreg[r];
            }
        }
        __syncthreads();
        cnt = s_num;
    } else {
        // ---- Fallback (statistically never): full strided rescan with ladder.
        if (tid < NLAD) s_pcnt[tid] = 0;
        __syncthreads();
        const float PL[NLAD] = {0.9950f, 0.9925f, 0.9900f, 0.9875f, 0.9850f,
                                0.98f, 0.96f, 0.92f, 0.84f, 0.68f, 0.50f};
        const float* col = scores + (size_t)b * PERB + c;
        int lc[NLAD];
        #pragma unroll
        for (int l = 0; l < NLAD; l++) lc[l] = 0;
        for (int i = tid; i < ROWS; i += 256) {
            float v = col[(size_t)i * NCLS];
            #pragma unroll
            for (int l = 0; l < NLAD; l++) lc[l] += (v > PL[l]);
        }
        #pragma unroll
        for (int l = 0; l < NLAD; l++) {
            int ws = __reduce_add_sync(0xffffffffu, lc[l]);
            if (lane == 0 && ws) atomicAdd(&s_pcnt[l], ws);
        }
        __syncthreads();
        const int n05 = s_pcnt[NLAD - 1];
        const int target = (n05 < TOPK) ? n05 : TOPK;
        float pivot = 0.50f;
        #pragma unroll
        for (int l = NLAD - 1; l >= 0; l--)
            if (s_pcnt[l] >= target) pivot = PL[l];
        for (int i = tid; i < ROWS; i += 256) {
            float v = col[(size_t)i * NCLS];
            if (v > pivot) {
                int pos = atomicAdd(&s_num, 1);
                if (pos < CAP) keys[pos] = make_key(v, i);
            }
        }
        __syncthreads();
        cnt = s_num; if (cnt > CAP) cnt = CAP;
    }

    // ---- Sort descending. Register/shuffle bitonic for cnt <= 256.
    if (cnt <= 256) {
        for (int i = cnt + tid; i < 256; i += 256) keys[i] = 0ull;
        __syncthreads();
        unsigned long long key = keys[tid];
        #pragma unroll
        for (int k = 2; k <= 256; k <<= 1) {
            #pragma unroll
            for (int j = k >> 1; j > 0; j >>= 1) {
                unsigned long long other;
                if (j >= 32) {
                    keys[tid] = key;
                    __syncthreads();
                    other = keys[tid ^ j];
                    __syncthreads();
                } else {
                    other = __shfl_xor_sync(0xffffffffu, key, j);
                }
                bool keep_max = ((tid & k) == 0) == ((tid & j) == 0);
                key = ((key > other) == keep_max) ? key : other;
            }
        }
        keys[tid] = key;
        __syncthreads();
    } else {
        int P = 512; while (P < cnt) P <<= 1;
        for (int i = cnt + tid; i < P; i += 256) keys[i] = 0ull;
        __syncthreads();
        for (int k = 2; k <= P; k <<= 1) {
            for (int j = k >> 1; j > 0; j >>= 1) {
                for (int i = tid; i < P; i += 256) {
                    int l = i ^ j;
                    if (l > i) {
                        unsigned long long a = keys[i], d = keys[l];
                        bool sw = ((i & k) == 0) ? (a < d) : (a > d);
                        if (sw) { keys[i] = d; keys[l] = a; }
                    }
                }
                __syncthreads();
            }
        }
    }

    const int n_top = (cnt < TOPK) ? cnt : TOPK;

    // ---- Gather boxes for the top-200; zero the padded sup array
    for (int k = tid; k < (TOPK + 1) * KW8 / 4; k += 256)
        ((uint4*)sup)[k] = make_uint4(0u, 0u, 0u, 0u);
    for (int k = tid; k < TOPK; k += 256) {
        if (k < n_top) {
            unsigned long long key = keys[k];
            int idx = (int)(~(unsigned int)(key & 0xffffffffull));
            float4 bb = ((const float4*)boxes)[(size_t)b * ROWS + idx];
            s_box4[k] = bb;
            s_area[k] = (bb.z - bb.x) * (bb.w - bb.y);
            s_sc[k]   = __uint_as_float((unsigned int)(key >> 32));
        } else {
            s_box4[k] = make_float4(0.f, 0.f, 0.f, 0.f);
            s_area[k] = 0.f; s_sc[k] = 0.f;
        }
    }
    __syncthreads();

    // ---- Suppression bitmask: one warp per row, ballot per 32-bit word.
    //      Diagonal word / full middle words / partial last word split so the
    //      bulk iterations carry no per-lane bounds tests.
    if (n_top > 0) {
        const int wlast = (n_top - 1) >> 5;
        for (int r = wid; r < n_top; r += 8) {
            const float4 bi = s_box4[r];
            const float  ai = s_area[r];
            const int    w0 = r >> 5;
            // diagonal word (j > r and j < n_top checks)
            {
                int j = (w0 << 5) + lane;
                bool hit = false;
                if (j > r && j < n_top) {
                    float4 bj = s_box4[j];
                    float xx1 = fmaxf(bi.x, bj.x), yy1 = fmaxf(bi.y, bj.y);
                    float xx2 = fminf(bi.z, bj.z), yy2 = fminf(bi.w, bj.w);
                    float inter = fmaxf(0.f, xx2 - xx1) * fmaxf(0.f, yy2 - yy1);
                    if (inter > 0.f) {
                        float un = (ai + s_area[j]) - inter;
                        hit = (inter / un) > 0.5f;
                    }
                }
                unsigned int m = __ballot_sync(0xffffffffu, hit);
                if (lane == 0) sup[r * KW8 + w0] = m;
            }
            // full middle words (no checks)
            for (int w = w0 + 1; w < wlast; w++) {
                int j = (w << 5) + lane;
                float4 bj = s_box4[j];
                float xx1 = fmaxf(bi.x, bj.x), yy1 = fmaxf(bi.y, bj.y);
                float xx2 = fminf(bi.z, bj.z), yy2 = fminf(bi.w, bj.w);
                float inter = fmaxf(0.f, xx2 - xx1) * fmaxf(0.f, yy2 - yy1);
                bool hit = false;
                if (inter > 0.f) {
                    float un = (ai + s_area[j]) - inter;
                    hit = (inter / un) > 0.5f;
                }
                unsigned int m = __ballot_sync(0xffffffffu, hit);
                if (lane == 0) sup[r * KW8 + w] = m;
            }
            // last (possibly partial) word
            if (wlast > w0) {
                int j = (wlast << 5) + lane;
                bool hit = false;
                if (j < n_top) {
                    float4 bj = s_box4[j];
                    float xx1 = fmaxf(bi.x, bj.x), yy1 = fmaxf(bi.y, bj.y);
                    float xx2 = fminf(bi.z, bj.z), yy2 = fminf(bi.w, bj.w);
                    float inter = fmaxf(0.f, xx2 - xx1) * fmaxf(0.f, yy2 - yy1);
                    if (inter > 0.f) {
                        float un = (ai + s_area[j]) - inter;
                        hit = (inter / un) > 0.5f;
                    }
                }
                unsigned int m = __ballot_sync(0xffffffffu, hit);
                if (lane == 0) sup[r * KW8 + wlast] = m;
            }
        }
    }
    __syncthreads();

    // ---- Serial greedy on thread 0: rows as 2x uint4, prefetch row i+1.
    if (tid == 0) {
        const uint4* sv = (const uint4*)sup;
        unsigned int rem[KW8];
        #pragma unroll
        for (int w = 0; w < KW8; w++) rem[w] = 0u;
        uint4 n0 = sv[0], n1 = sv[1];
        #pragma unroll
        for (int w0 = 0; w0 < KW; w0++) {
            for (int ii = 0; ii < 32; ii++) {
                int idx = w0 * 32 + ii;
                if (idx >= n_top) break;
                uint4 c0 = n0, c1 = n1;
                n0 = sv[(idx + 1) * 2];
                n1 = sv[(idx + 1) * 2 + 1];
                if (((rem[w0] >> ii) & 1u) == 0u) {
                    rem[0] |= c0.x; rem[1] |= c0.y; rem[2] |= c0.z; rem[3] |= c0.w;
                    rem[4] |= c1.x; rem[5] |= c1.y; rem[6] |= c1.z;
                }
            }
        }
        #pragma unroll
        for (int w = 0; w < KW; w++) s_keepw[w] = ~rem[w];
        g_ccnt[bc] = 0;   // self-clean for next replay
    }
    __syncthreads();

    // ---- Stage output rows in smem (reusing keys as scratch), then
    //      coalesced float4 copy to global.
    float* s_out = (float*)keys;   // 4800 B needed, 8192 B available
    if (tid < TOPK) {
        int k = tid;
        bool kp = (k < n_top) && (((s_keepw[k >> 5] >> (k & 31)) & 1u) != 0u);
        float4 bb = s_box4[k];
        float sc = s_sc[k], cl = (float)c;
        if (!kp) { bb = make_float4(0.f, 0.f, 0.f, 0.f); sc = 0.f; cl = 0.f; }
        s_out[k * 6 + 0] = bb.x; s_out[k * 6 + 1] = bb.y;
        s_out[k * 6 + 2] = bb.z; s_out[k * 6 + 3] = bb.w;
        s_out[k * 6 + 4] = sc;   s_out[k * 6 + 5] = cl;
    }
    __syncthreads();
    float4* o4 = (float4*)(out + (size_t)bc * (TOPK * 6));
    const float4* si4 = (const float4*)s_out;
    for (int t = tid; t < TOPK * 6 / 4; t += 256) o4[t] = si4[t];
}

// ---------------------------------------------------------------------------
extern "C" void kernel_launch(void* const* d_in, const int* in_sizes, int n_in,
                              void* d_out, int out_size) {
    const float* boxes  = (const float*)d_in[0];
    const float* scores = (const float*)d_in[1];
    if (n_in >= 2 && in_sizes[0] > in_sizes[1]) {  // scores is the bigger tensor
        boxes  = (const float*)d_in[1];
        scores = (const float*)d_in[0];
    }
    float* out = (float*)d_out;

    fused_kernel<<<NBC, 256>>>((const float4*)scores, boxes, scores, out);
}